// round 2
// baseline (speedup 1.0000x reference)
#include <cuda_runtime.h>
#include <cstdint>

#define BN 4096
#define CN 80
#define ERRN 4

// ---------------- scratch (static device arrays; no allocation) ----------------
__device__ int g_lid[BN];
__device__ int g_idx[2][BN][ERRN];

// ---------------- threefry2x32 (exact JAX semantics) ----------------
__host__ __device__ __forceinline__ uint32_t tf_rotl(uint32_t v, int r) {
    return (v << r) | (v >> (32 - r));
}

__host__ __device__ __forceinline__ void threefry2x32(uint32_t k0, uint32_t k1,
                                                      uint32_t c0, uint32_t c1,
                                                      uint32_t& o0, uint32_t& o1) {
    uint32_t ks0 = k0, ks1 = k1, ks2 = k0 ^ k1 ^ 0x1BD11BDAu;
    uint32_t x0 = c0 + ks0;
    uint32_t x1 = c1 + ks1;
#define TF_RND(r) { x0 += x1; x1 = tf_rotl(x1, r); x1 ^= x0; }
    TF_RND(13) TF_RND(15) TF_RND(26) TF_RND(6)
    x0 += ks1; x1 += ks2 + 1u;
    TF_RND(17) TF_RND(29) TF_RND(16) TF_RND(24)
    x0 += ks2; x1 += ks0 + 2u;
    TF_RND(13) TF_RND(15) TF_RND(26) TF_RND(6)
    x0 += ks0; x1 += ks1 + 3u;
    TF_RND(17) TF_RND(29) TF_RND(16) TF_RND(24)
    x0 += ks1; x1 += ks2 + 4u;
    TF_RND(13) TF_RND(15) TF_RND(26) TF_RND(6)
    x0 += ks2; x1 += ks0 + 5u;
#undef TF_RND
    o0 = x0; o1 = x1;
}

// ---------------- top-4 helpers ----------------
__device__ __forceinline__ void ins4(unsigned long long* t, unsigned long long c) {
    if (c > t[0])      { t[3] = t[2]; t[2] = t[1]; t[1] = t[0]; t[0] = c; }
    else if (c > t[1]) { t[3] = t[2]; t[2] = t[1]; t[1] = c; }
    else if (c > t[2]) { t[3] = t[2]; t[2] = c; }
    else if (c > t[3]) { t[3] = c; }
}

__device__ __forceinline__ void warp_merge4(unsigned long long* top) {
    for (int off = 16; off > 0; off >>= 1) {
        unsigned long long o0 = __shfl_xor_sync(0xFFFFFFFFu, top[0], off);
        unsigned long long o1 = __shfl_xor_sync(0xFFFFFFFFu, top[1], off);
        unsigned long long o2 = __shfl_xor_sync(0xFFFFFFFFu, top[2], off);
        unsigned long long o3 = __shfl_xor_sync(0xFFFFFFFFu, top[3], off);
        ins4(top, o0); ins4(top, o1); ins4(top, o2); ins4(top, o3);
    }
}

// ---------------- kernels ----------------
__global__ void k_labelid(const float* __restrict__ labels) {
    int i = blockIdx.x * blockDim.x + threadIdx.x;
    if (i < BN) {
        const float* row = labels + (size_t)i * CN;
        int id = 0;
        #pragma unroll 8
        for (int j = 0; j < CN; j++)
            if (row[j] > 0.5f) id = j;
        g_lid[i] = id;
    }
}

// grid (BN, 2), block 256. blockIdx.y selects key ks1 (it) / ks2 (ti).
// Partitionable random_bits for 32-bit dtype: bits[m] = x0 ^ x1 of
// threefry(key, (m>>32, m&0xffffffff)); here m = row*4096 + j < 2^32 so
// the hi counter word is 0. uniform's float map is monotone in bits>>9,
// so top-4 ranking uses the 23-bit integer; top_k ties -> lower j.
__global__ __launch_bounds__(256) void k_select(uint32_t a0, uint32_t a1,
                                                uint32_t b0, uint32_t b1) {
    const int row = blockIdx.x;
    const uint32_t kk0 = blockIdx.y ? b0 : a0;
    const uint32_t kk1 = blockIdx.y ? b1 : a1;
    const int myLid = g_lid[row];
    const uint32_t base = (uint32_t)row * (uint32_t)BN;

    unsigned long long top[4] = {0ull, 0ull, 0ull, 0ull};

    #pragma unroll
    for (int t = 0; t < BN / 256; t++) {
        int j = threadIdx.x + t * 256;
        uint32_t o0, o1;
        threefry2x32(kk0, kk1, 0u, base + (uint32_t)j, o0, o1);
        uint32_t val = (o0 ^ o1) >> 9;               // 23-bit mantissa bits
        bool valid = (g_lid[j] != myLid);            // symmetric neg mask
        unsigned long long cand =
            valid ? ((((unsigned long long)val + 1ull) << 12) |
                     (unsigned long long)(BN - 1 - j))
                  : 0ull;
        ins4(top, cand);
    }

    warp_merge4(top);

    __shared__ unsigned long long sm[32];
    int wid = threadIdx.x >> 5, lane = threadIdx.x & 31;
    if (lane == 0) {
        sm[wid * 4 + 0] = top[0];
        sm[wid * 4 + 1] = top[1];
        sm[wid * 4 + 2] = top[2];
        sm[wid * 4 + 3] = top[3];
    }
    __syncthreads();

    if (threadIdx.x < 32) {
        unsigned long long t2[4] = {sm[threadIdx.x], 0ull, 0ull, 0ull};
        warp_merge4(t2);
        if (threadIdx.x < 4) {
            g_idx[blockIdx.y][row][threadIdx.x] =
                (BN - 1) - (int)(t2[threadIdx.x] & 0xFFFull);
        }
    }
}

__global__ void k_zero(float* out, int n) {
    int i = blockIdx.x * blockDim.x + threadIdx.x;
    if (i < n) out[i] = 0.0f;
}

__device__ __forceinline__ float warp_sum(float s) {
    for (int off = 16; off > 0; off >>= 1)
        s += __shfl_xor_sync(0xFFFFFFFFu, s, off);
    return s;
}

__device__ __forceinline__ float dist4(float4 a, float4 b) {
    float dx = a.x - b.x, dy = a.y - b.y, dz = a.z - b.z, dw = a.w - b.w;
    float s = dx * dx + dy * dy + dz * dz + dw * dw;
    s = warp_sum(s);
    return sqrtf(fmaxf(s, 0.0f));
}

// one warp per row; 128 threads = 4 warps per block; grid BN/4.
__global__ __launch_bounds__(128) void k_loss(const float* __restrict__ img,
                                              const float* __restrict__ txt,
                                              float* __restrict__ out) {
    int gwarp = (blockIdx.x * blockDim.x + threadIdx.x) >> 5;
    int lane = threadIdx.x & 31;
    if (gwarp >= BN) return;
    const int i = gwarp;

    const float4* img4 = (const float4*)img;
    const float4* txt4 = (const float4*)txt;

    float4 ai = img4[i * 32 + lane];
    float4 ti = txt4[i * 32 + lane];

    float pos = dist4(ai, ti);  // dist_it[i][i] == dist_ti[i][i]

    float acc = 0.0f;
    #pragma unroll
    for (int k = 0; k < ERRN; k++) {
        int j = g_idx[0][i][k];                    // image i vs text j
        float4 tj = txt4[j * 32 + lane];
        float neg = dist4(ai, tj);
        acc += fmaxf(pos - neg + 1.0f, 0.0f);
    }
    #pragma unroll
    for (int k = 0; k < ERRN; k++) {
        int j = g_idx[1][i][k];                    // text i vs image j
        float4 ij = img4[j * 32 + lane];
        float neg = dist4(ti, ij);
        acc += fmaxf(pos - neg + 1.0f, 0.0f);
    }

    if (lane == 0)
        atomicAdd(out, acc * (1.0f / (float)(BN * ERRN)));
}

// ---------------- launch ----------------
extern "C" void kernel_launch(void* const* d_in, const int* in_sizes, int n_in,
                              void* d_out, int out_size) {
    const float* img    = (const float*)d_in[0];
    const float* txt    = (const float*)d_in[1];
    const float* labels = (const float*)d_in[2];
    float* out = (float*)d_out;

    // Derive ks1, ks2 on host: jax.random.key(42) -> (0,42);
    // partitionable split (foldlike): key_i = threefry((0,42), (0, i)).
    uint32_t a0, a1, b0, b1;
    threefry2x32(0u, 42u, 0u, 0u, a0, a1);  // ks1 (image->text scores)
    threefry2x32(0u, 42u, 0u, 1u, b0, b1);  // ks2 (text->image scores)

    k_labelid<<<(BN + 255) / 256, 256>>>(labels);

    dim3 gsel(BN, 2);
    k_select<<<gsel, 256>>>(a0, a1, b0, b1);

    k_zero<<<(out_size + 127) / 128, 128>>>(out, out_size);
    k_loss<<<BN / 4, 128>>>(img, txt, out);
}

// round 3
// speedup vs baseline: 1.2599x; 1.2599x over previous
#include <cuda_runtime.h>
#include <cstdint>

#define BN 4096
#define CN 80
#define ERRN 4

// ---------------- scratch ----------------
__device__ unsigned char g_lid8[BN];
__device__ int g_idx[2][BN][ERRN];

// ---------------- threefry2x32 (exact JAX semantics) ----------------
__host__ __device__ __forceinline__ uint32_t tf_rotl(uint32_t v, int r) {
    return (v << r) | (v >> (32 - r));
}

// full version (host key derivation + generic use)
__host__ __device__ __forceinline__ void threefry2x32(uint32_t k0, uint32_t k1,
                                                      uint32_t c0, uint32_t c1,
                                                      uint32_t& o0, uint32_t& o1) {
    uint32_t ks0 = k0, ks1 = k1, ks2 = k0 ^ k1 ^ 0x1BD11BDAu;
    uint32_t x0 = c0 + ks0;
    uint32_t x1 = c1 + ks1;
#define TF_RND(r) { x0 += x1; x1 = tf_rotl(x1, r); x1 ^= x0; }
    TF_RND(13) TF_RND(15) TF_RND(26) TF_RND(6)
    x0 += ks1; x1 += ks2 + 1u;
    TF_RND(17) TF_RND(29) TF_RND(16) TF_RND(24)
    x0 += ks2; x1 += ks0 + 2u;
    TF_RND(13) TF_RND(15) TF_RND(26) TF_RND(6)
    x0 += ks0; x1 += ks1 + 3u;
    TF_RND(17) TF_RND(29) TF_RND(16) TF_RND(24)
    x0 += ks1; x1 += ks2 + 4u;
    TF_RND(13) TF_RND(15) TF_RND(26) TF_RND(6)
    x0 += ks2; x1 += ks0 + 5u;
#undef TF_RND
    o0 = x0; o1 = x1;
}

// Hot-path: returns x0^x1 of threefry((k0,k1),(0,c1)).
// Rounds alternate two rotl implementations to balance alu vs fma pipes:
//   mul form:  w = x1 * 2^r (IMAD.WIDE, fma pipe); x1 = lo ^ hi ^ x0 (one LOP3)
//   shf form:  x1 = funnelshift(x1) ^ x0 (SHF + LOP3, alu pipe)
__device__ __forceinline__ uint32_t tf_bits(uint32_t k0, uint32_t k1,
                                            uint32_t ks2, uint32_t c1) {
    uint32_t x0 = k0;
    uint32_t x1 = c1 + k1;
#define RND_MUL(r) { x0 += x1; \
    unsigned long long w = (unsigned long long)x1 * (1ull << (r)); \
    x1 = (uint32_t)w ^ (uint32_t)(w >> 32) ^ x0; }
#define RND_SHF(r) { x0 += x1; x1 = __funnelshift_l(x1, x1, (r)) ^ x0; }
#define GRP_A RND_MUL(13) RND_SHF(15) RND_MUL(26) RND_SHF(6)
#define GRP_B RND_MUL(17) RND_SHF(29) RND_MUL(16) RND_SHF(24)
    GRP_A
    x0 += k1;  x1 += ks2 + 1u;
    GRP_B
    x0 += ks2; x1 += k0 + 2u;
    GRP_A
    x0 += k0;  x1 += k1 + 3u;
    GRP_B
    x0 += k1;  x1 += ks2 + 4u;
    GRP_A
    x0 += ks2; x1 += k0 + 5u;
#undef GRP_A
#undef GRP_B
#undef RND_MUL
#undef RND_SHF
    return x0 ^ x1;
}

// ---------------- top-4 helpers (cold path only) ----------------
__device__ __forceinline__ void ins4(unsigned long long* t, unsigned long long c) {
    if (c > t[0])      { t[3] = t[2]; t[2] = t[1]; t[1] = t[0]; t[0] = c; }
    else if (c > t[1]) { t[3] = t[2]; t[2] = t[1]; t[1] = c; }
    else if (c > t[2]) { t[3] = t[2]; t[2] = c; }
    else if (c > t[3]) { t[3] = c; }
}

__device__ __forceinline__ void warp_merge4(unsigned long long* top) {
    for (int off = 16; off > 0; off >>= 1) {
        unsigned long long o0 = __shfl_xor_sync(0xFFFFFFFFu, top[0], off);
        unsigned long long o1 = __shfl_xor_sync(0xFFFFFFFFu, top[1], off);
        unsigned long long o2 = __shfl_xor_sync(0xFFFFFFFFu, top[2], off);
        unsigned long long o3 = __shfl_xor_sync(0xFFFFFFFFu, top[3], off);
        ins4(top, o0); ins4(top, o1); ins4(top, o2); ins4(top, o3);
    }
}

// ---------------- kernels ----------------
// one warp per row; block 256 = 8 rows; grid 512. Also zeroes d_out.
__global__ __launch_bounds__(256) void k_labelid(const float* __restrict__ labels,
                                                 float* __restrict__ out,
                                                 int out_size) {
    int warp = (blockIdx.x * blockDim.x + threadIdx.x) >> 5;
    int lane = threadIdx.x & 31;
    if (blockIdx.x == 0 && threadIdx.x < out_size) out[threadIdx.x] = 0.0f;
    if (warp >= BN) return;
    const float* row = labels + (size_t)warp * CN;
    unsigned best = 0;
    #pragma unroll
    for (int k = 0; k < 3; k++) {
        int j = lane + k * 32;
        if (j < CN && row[j] > 0.5f) best = (unsigned)j;
    }
    best = __reduce_max_sync(0xFFFFFFFFu, best);
    if (lane == 0) g_lid8[warp] = (unsigned char)best;
}

// grid 4096 (one block per row, both directions), block 256.
// Thread t owns contiguous j in [16t, 16t+16).
// Phase 1: per-thread top-1 via 32-bit unsigned max on ((v+1)<<4)|(15-s).
// Phase 2: block top-4 of packed per-thread bests ((v+1)<<12)|(4095-j).
// Phase 3: rescan the <=4 owner threads with exact u64 ins4, merge.
__global__ __launch_bounds__(256) void k_select(uint32_t a0, uint32_t a1,
                                                uint32_t b0, uint32_t b1) {
    const int row = blockIdx.x;
    const int tid = threadIdx.x;
    const uint32_t ksA2 = a0 ^ a1 ^ 0x1BD11BDAu;
    const uint32_t ksB2 = b0 ^ b1 ^ 0x1BD11BDAu;

    const uint32_t mylid = (uint32_t)g_lid8[row];
    const uint4 l4 = reinterpret_cast<const uint4*>(g_lid8)[tid];
    const uint32_t lw[4] = {l4.x, l4.y, l4.z, l4.w};

    const uint32_t cbase = (uint32_t)row * (uint32_t)BN + (uint32_t)tid * 16u;

    uint32_t bestA = 0u, bestB = 0u;
    #pragma unroll
    for (int s = 0; s < 16; s++) {
        uint32_t bitsA = tf_bits(a0, a1, ksA2, cbase + (uint32_t)s);
        uint32_t bitsB = tf_bits(b0, b1, ksB2, cbase + (uint32_t)s);
        uint32_t lid_s = __byte_perm(lw[s >> 2], 0u, 0x7770u | (unsigned)(s & 3));
        bool valid = (lid_s != mylid);
        // cand = ((v+1)<<4) | (15-s)  with v = bits>>9 ; invalid -> 0
        uint32_t cA = ((bitsA >> 9) << 4) + (uint32_t)(31 - s);
        uint32_t cB = ((bitsB >> 9) << 4) + (uint32_t)(31 - s);
        cA = valid ? cA : 0u;
        cB = valid ? cB : 0u;
        bestA = max(bestA, cA);
        bestB = max(bestB, cB);
    }

    // pack per-thread best as ((v+1)<<12) | (4095 - j); 0 if no valid cand
    __shared__ unsigned long long sA[256], sB[256];
    {
        int jsA = 15 - (int)(bestA & 15u);
        int jsB = 15 - (int)(bestB & 15u);
        unsigned long long pA = (bestA >= 16u)
            ? (((unsigned long long)(bestA >> 4)) << 12) |
              (unsigned long long)(BN - 1 - (tid * 16 + jsA)) : 0ull;
        unsigned long long pB = (bestB >= 16u)
            ? (((unsigned long long)(bestB >> 4)) << 12) |
              (unsigned long long)(BN - 1 - (tid * 16 + jsB)) : 0ull;
        sA[tid] = pA;
        sB[tid] = pB;
    }
    __syncthreads();

    const int wid = tid >> 5, lane = tid & 31;
    if (wid < 2) {
        const unsigned long long* src = wid ? sB : sA;
        const uint32_t kk0 = wid ? b0 : a0;
        const uint32_t kk1 = wid ? b1 : a1;
        const uint32_t kks2 = wid ? ksB2 : ksA2;

        unsigned long long top[4] = {0ull, 0ull, 0ull, 0ull};
        #pragma unroll
        for (int k = 0; k < 8; k++) ins4(top, src[lane + 32 * k]);
        warp_merge4(top);  // all lanes converge to block top-4 of bests

        // phase 3: lanes 0..3 rescan their owner thread exactly
        unsigned long long mytop[4] = {0ull, 0ull, 0ull, 0ull};
        if (lane < 4 && top[lane] != 0ull) {
            int j0 = BN - 1 - (int)(top[lane] & 0xFFFull);
            int to = j0 >> 4;  // owner thread
            uint4 ol4 = reinterpret_cast<const uint4*>(g_lid8)[to];
            uint32_t olw[4] = {ol4.x, ol4.y, ol4.z, ol4.w};
            uint32_t ob = (uint32_t)row * (uint32_t)BN + (uint32_t)to * 16u;
            #pragma unroll
            for (int s = 0; s < 16; s++) {
                uint32_t bits = tf_bits(kk0, kk1, kks2, ob + (uint32_t)s);
                uint32_t lid_s =
                    __byte_perm(olw[s >> 2], 0u, 0x7770u | (unsigned)(s & 3));
                if (lid_s != mylid) {
                    unsigned long long pv =
                        (((unsigned long long)((bits >> 9) + 1u)) << 12) |
                        (unsigned long long)(BN - 1 - (to * 16 + s));
                    ins4(mytop, pv);
                }
            }
        }
        warp_merge4(mytop);  // lanes >=4 contribute zeros
        if (lane < ERRN)
            g_idx[wid][row][lane] = BN - 1 - (int)(mytop[lane] & 0xFFFull);
    }
}

__device__ __forceinline__ float warp_sum(float s) {
    for (int off = 16; off > 0; off >>= 1)
        s += __shfl_xor_sync(0xFFFFFFFFu, s, off);
    return s;
}

__device__ __forceinline__ float dist4(float4 a, float4 b) {
    float dx = a.x - b.x, dy = a.y - b.y, dz = a.z - b.z, dw = a.w - b.w;
    float s = dx * dx + dy * dy + dz * dz + dw * dw;
    s = warp_sum(s);
    return sqrtf(fmaxf(s, 0.0f));
}

// one warp per (row, dir); block 256 = 8 warps = 4 rows; grid 1024.
__global__ __launch_bounds__(256) void k_loss(const float* __restrict__ img,
                                              const float* __restrict__ txt,
                                              float* __restrict__ out) {
    const int w = threadIdx.x >> 5;
    const int lane = threadIdx.x & 31;
    const int i = blockIdx.x * 4 + (w >> 1);
    const int dir = w & 1;

    const float4* img4 = (const float4*)img;
    const float4* txt4 = (const float4*)txt;

    float4 ai = img4[i * 32 + lane];
    float4 ti = txt4[i * 32 + lane];
    float pos = dist4(ai, ti);

    const float4* nsrc = dir ? img4 : txt4;
    float4 anc = dir ? ti : ai;

    float acc = 0.0f;
    #pragma unroll
    for (int k = 0; k < ERRN; k++) {
        int j = g_idx[dir][i][k];
        float4 bj = nsrc[j * 32 + lane];
        float neg = dist4(anc, bj);
        acc += fmaxf(pos - neg + 1.0f, 0.0f);
    }

    __shared__ float ssum[8];
    if (lane == 0) ssum[w] = acc;
    __syncthreads();
    if (threadIdx.x == 0) {
        float t = 0.0f;
        #pragma unroll
        for (int k = 0; k < 8; k++) t += ssum[k];
        atomicAdd(out, t * (1.0f / (float)(BN * ERRN)));
    }
}

// ---------------- launch ----------------
extern "C" void kernel_launch(void* const* d_in, const int* in_sizes, int n_in,
                              void* d_out, int out_size) {
    const float* img    = (const float*)d_in[0];
    const float* txt    = (const float*)d_in[1];
    const float* labels = (const float*)d_in[2];
    float* out = (float*)d_out;

    // jax.random.key(42) -> (0,42); partitionable foldlike split:
    // key_i = threefry((0,42), (0, i)).
    uint32_t a0, a1, b0, b1;
    threefry2x32(0u, 42u, 0u, 0u, a0, a1);  // ks1 (image->text scores)
    threefry2x32(0u, 42u, 0u, 1u, b0, b1);  // ks2 (text->image scores)

    k_labelid<<<512, 256>>>(labels, out, out_size);
    k_select<<<BN, 256>>>(a0, a1, b0, b1);
    k_loss<<<BN / 4, 256>>>(img, txt, out);
}